// round 5
// baseline (speedup 1.0000x reference)
#include <cuda_runtime.h>
#include <cuda_bf16.h>
#include <cstdint>

// ---------------- problem constants ----------------
#define N_TOK   262144
#define TOPK    2
#define NSLOTS  (N_TOK * TOPK)     // 524288
#define D       128
#define NEXP    8
#define TS      128                // slots per tile
#define MAXTILES (NSLOTS / TS + NEXP)   // 4104
#define NTHREADS 512

// ---------------- device scratch ----------------
__device__ float g_yscat[(size_t)NSLOTS * D];    // gated per-slot outputs (256 MiB)
__device__ uint4 g_whp[NEXP * 2048];             // W hi bf16, packed (32KB/expert)
__device__ uint4 g_wlp[NEXP * 2048];             // W lo bf16, packed
__device__ int   g_seg[NEXP + 1];
__device__ int   g_tile_e[MAXTILES];
__device__ int   g_tile_s[MAXTILES];
__device__ int   g_ntiles;
__device__ unsigned g_bar;                       // grid barrier (reset by seg_kernel)

// ---------------- helpers ----------------
__device__ __forceinline__ uint32_t smem_u32(const void* p) {
    uint32_t a;
    asm("{ .reg .u64 t; cvta.to.shared.u64 t, %1; cvt.u32.u64 %0, t; }" : "=r"(a) : "l"(p));
    return a;
}
__device__ __forceinline__ void ldsm_x4(uint32_t* r, uint32_t addr) {
    asm volatile("ldmatrix.sync.aligned.m8n8.x4.shared.b16 {%0,%1,%2,%3}, [%4];"
        : "=r"(r[0]), "=r"(r[1]), "=r"(r[2]), "=r"(r[3]) : "r"(addr));
}
__device__ __forceinline__ void mma_bf16(float* c, const uint32_t* a, uint32_t b0, uint32_t b1) {
    asm volatile("mma.sync.aligned.m16n8k16.row.col.f32.bf16.bf16.f32 "
        "{%0,%1,%2,%3}, {%4,%5,%6,%7}, {%8,%9}, {%0,%1,%2,%3};"
        : "+f"(c[0]), "+f"(c[1]), "+f"(c[2]), "+f"(c[3])
        : "r"(a[0]), "r"(a[1]), "r"(a[2]), "r"(a[3]), "r"(b0), "r"(b1));
}
#define CP_ASYNC16(dst, src) \
    asm volatile("cp.async.cg.shared.global [%0], [%1], 16;" :: "r"(dst), "l"(src))
#define CP_COMMIT()  asm volatile("cp.async.commit_group;" ::: "memory")
#define CP_WAIT0()   asm volatile("cp.async.wait_group 0;" ::: "memory")

// convert 8 fp32 -> hi/lo bf16 packs (16 B each)
__device__ __forceinline__ void cvt8(const float* v, uint4& hv, uint4& lv) {
    __nv_bfloat16 h[8]; float l[8];
#pragma unroll
    for (int i = 0; i < 8; i++) {
        h[i] = __float2bfloat16_rn(v[i]);
        l[i] = v[i] - __bfloat162float(h[i]);
    }
    uint32_t hu[4], lu[4];
#pragma unroll
    for (int i = 0; i < 4; i++) {
        __nv_bfloat162 hp = __halves2bfloat162(h[2 * i], h[2 * i + 1]);
        hu[i] = *reinterpret_cast<uint32_t*>(&hp);
        __nv_bfloat162 lp = __floats2bfloat162_rn(l[2 * i], l[2 * i + 1]);
        lu[i] = *reinterpret_cast<uint32_t*>(&lp);
    }
    hv = make_uint4(hu[0], hu[1], hu[2], hu[3]);
    lv = make_uint4(lu[0], lu[1], lu[2], lu[3]);
}

// -------------------------------------------------------------------
// Prologue 1: weight fp32 [E, d_out, d_in] -> packed bf16 hi/lo
// -------------------------------------------------------------------
__global__ void wconv_kernel(const float* __restrict__ w) {
    int e = blockIdx.x;
    int tid = threadIdx.x;
    int row = tid >> 1;
    int half = tid & 1;
    const float* wr = w + ((size_t)e * D + row) * D;
    uint4* whe = g_whp + e * 2048;
    uint4* wle = g_wlp + e * 2048;
#pragma unroll
    for (int g = 0; g < 8; g++) {
        int col0 = half * 64 + g * 8;
        float v[8];
#pragma unroll
        for (int i = 0; i < 8; i++) v[i] = wr[col0 + i];
        uint4 hv, lv;
        cvt8(v, hv, lv);
        int idx = row * 16 + half * 8 + g;
        whe[idx] = hv;
        wle[idx] = lv;
    }
}

// -------------------------------------------------------------------
// Prologue 2: expert segments + dense tile map + barrier reset
// -------------------------------------------------------------------
__global__ void seg_kernel(const int* __restrict__ sei) {
    __shared__ int seg[NEXP + 1];
    __shared__ int cnts[NEXP];
    int t = threadIdx.x;
    if (t == 0) g_bar = 0;
    if (t <= NEXP) {
        int lo = 0, hi = NSLOTS;
        while (lo < hi) {
            int mid = (lo + hi) >> 1;
            if (sei[mid] < t) lo = mid + 1; else hi = mid;
        }
        seg[t] = lo;
        g_seg[t] = lo;
    }
    __syncthreads();
    if (t < NEXP) cnts[t] = (seg[t + 1] - seg[t] + TS - 1) / TS;
    __syncthreads();
    if (t < NEXP) {
        int off = 0;
        for (int i = 0; i < t; i++) off += cnts[i];
        int s = seg[t];
        for (int i = 0; i < cnts[t]; i++) {
            g_tile_e[off + i] = t;
            g_tile_s[off + i] = s + i * TS;
        }
    }
    if (t == 0) {
        int tot = 0;
        for (int i = 0; i < NEXP; i++) tot += cnts[i];
        g_ntiles = tot;
    }
}

// -------------------------------------------------------------------
// SMEM layout
// -------------------------------------------------------------------
#define XROWB 272
#define IMGB  (128 * XROWB)          // 34816
#define RAWS  528
#define RAWB  (128 * RAWS)           // 67584
#define OFF_SHF 0
#define OFF_SHG 512
#define OFF_RAW 1024
#define OFF_XH  (OFF_RAW + RAWB)
#define OFF_XL  (OFF_XH + IMGB)
#define OFF_WH  (OFF_XL + IMGB)
#define OFF_WL  (OFF_WH + IMGB)
#define SMEM_TOTAL (OFF_WL + IMGB)   // 207872

// issue cp.async gather: thread covers quarter-row (8 x 16B)
__device__ __forceinline__ void issue_x(const float* __restrict__ x, int tok,
                                        int tid, uint32_t sb) {
    int r = tid >> 2, q = tid & 3;
    uint32_t dst = sb + OFF_RAW + (uint32_t)r * RAWS + q * 128;
    const char* src = (const char*)(x + (size_t)tok * D) + q * 128;
#pragma unroll
    for (int c = 0; c < 8; c++)
        CP_ASYNC16(dst + c * 16, src + c * 16);
}

// -------------------------------------------------------------------
// Fused persistent kernel: MMA all tiles -> grid barrier -> combine
// -------------------------------------------------------------------
extern "C" __global__ void __launch_bounds__(NTHREADS, 1)
moe_fused_kernel(const float* __restrict__ x,
                 const float* __restrict__ gates,
                 const int*   __restrict__ ssi,
                 float* __restrict__ out) {
    int ntiles = g_ntiles;
    int nc = gridDim.x;
    int per = ntiles / nc, rem = ntiles % nc;
    int t0 = blockIdx.x * per + min((int)blockIdx.x, rem);
    int t1 = t0 + per + (blockIdx.x < rem ? 1 : 0);

    extern __shared__ char smem[];
    uint32_t sb = smem_u32(smem);
    int*   sh_f = (int*)(smem + OFF_SHF);
    float* sh_g = (float*)(smem + OFF_SHG);

    int tid = threadIdx.x;
    int wid = tid >> 5;
    int lane = tid & 31;
    int r = tid >> 2;                 // staging row
    int q = tid & 3;                  // quarter within row

    // warp tile coords: 4x4 map, each warp 32 slots x 32 outs
    int wr = wid & 3;
    int wc = wid >> 2;
    int lrow = (lane & 7) | (lane & 8);
    int kby  = (lane >> 4) * 16;
    uint32_t aA = sb + OFF_XH + (uint32_t)(wr * 32 + lrow) * XROWB + kby;
    uint32_t aB = sb + OFF_WH + (uint32_t)(wc * 32 + lrow) * XROWB + kby;
    const uint32_t DL = IMGB;

    if (t0 < t1) {
        // ---- prime tile t0 ----
        int e  = g_tile_e[t0];
        int s0 = g_tile_s[t0];
        int cnt = min(TS, g_seg[e + 1] - s0);
        int   fcur = (r < cnt) ? ssi[s0 + r] : 0;
        float gcur = (r < cnt) ? gates[fcur] : 0.f;
        issue_x(x, fcur >> 1, tid, sb);
        CP_COMMIT();

        int staged_e = -1;

        for (int t = t0; t < t1; t++) {
            bool havenext = (t + 1 < t1);
            int en = e, s0n = s0, cntn = cnt, fnxt = 0; float gnxt = 0.f;
            if (havenext) {
                en  = g_tile_e[t + 1];
                s0n = g_tile_s[t + 1];
                cntn = min(TS, g_seg[en + 1] - s0n);
                fnxt = (r < cntn) ? ssi[s0n + r] : 0;
                gnxt = (r < cntn) ? gates[fnxt] : 0.f;
            }

            CP_WAIT0();
            __syncthreads();

            // ---- stage W on expert change (rare) ----
            if (e != staged_e) {
                const uint4* whe = g_whp + e * 2048;
                const uint4* wle = g_wlp + e * 2048;
#pragma unroll
                for (int i = 0; i < 4; i++) {
                    int cid = tid + NTHREADS * i;
                    int row = cid >> 4;
                    int w16 = cid & 15;
                    uint32_t doff = row * XROWB + w16 * 16;
                    *(uint4*)(smem + OFF_WH + doff) = whe[cid];
                    *(uint4*)(smem + OFF_WL + doff) = wle[cid];
                }
                staged_e = e;
            }

            // ---- metadata to smem ----
            if (q == 0) {
                sh_f[r] = fcur;
                sh_g[r] = gcur;
            }

            // ---- convert raw fp32 -> bf16 hi/lo images (quarter-row/thread) ----
            {
                const char* rp = smem + OFF_RAW + (uint32_t)r * RAWS + q * 128;
                char* xh = smem + OFF_XH;
                char* xl = smem + OFF_XL;
#pragma unroll
                for (int g = 0; g < 4; g++) {
                    float4 a = *(const float4*)(rp + g * 32);
                    float4 b = *(const float4*)(rp + g * 32 + 16);
                    float v[8] = {a.x, a.y, a.z, a.w, b.x, b.y, b.z, b.w};
                    uint4 hv, lv;
                    cvt8(v, hv, lv);
                    uint32_t off = (uint32_t)r * XROWB + (q * 32 + g * 8) * 2;
                    *(uint4*)(xh + off) = hv;
                    *(uint4*)(xl + off) = lv;
                }
            }
            __syncthreads();

            // ---- kick gather for t+1 ----
            if (havenext) {
                issue_x(x, fnxt >> 1, tid, sb);
                CP_COMMIT();
            }

            // ---- MMA: 3-term bf16 split, warp 32x32 ----
            float acc[2][4][4];
#pragma unroll
            for (int mt = 0; mt < 2; mt++)
#pragma unroll
                for (int nt = 0; nt < 4; nt++)
#pragma unroll
                    for (int i = 0; i < 4; i++) acc[mt][nt][i] = 0.f;

#pragma unroll
            for (int kk = 0; kk < 8; kk++) {
                uint32_t kb = kk * 32;
                uint32_t ah[2][4], al[2][4];
                ldsm_x4(ah[0], aA + kb);
                ldsm_x4(ah[1], aA + 16 * XROWB + kb);
                ldsm_x4(al[0], aA + DL + kb);
                ldsm_x4(al[1], aA + DL + 16 * XROWB + kb);
#pragma unroll
                for (int ng = 0; ng < 2; ng++) {
                    uint32_t bh[4], bl[4];
                    ldsm_x4(bh, aB + ng * 16 * XROWB + kb);
                    ldsm_x4(bl, aB + DL + ng * 16 * XROWB + kb);
#pragma unroll
                    for (int mt = 0; mt < 2; mt++) {
                        mma_bf16(acc[mt][2 * ng],     ah[mt], bh[0], bh[2]);
                        mma_bf16(acc[mt][2 * ng + 1], ah[mt], bh[1], bh[3]);
                        mma_bf16(acc[mt][2 * ng],     al[mt], bh[0], bh[2]);
                        mma_bf16(acc[mt][2 * ng + 1], al[mt], bh[1], bh[3]);
                        mma_bf16(acc[mt][2 * ng],     ah[mt], bl[0], bl[2]);
                        mma_bf16(acc[mt][2 * ng + 1], ah[mt], bl[1], bl[3]);
                    }
                }
            }

            // ---- epilogue: gate + scatter ----
            {
                int row_lo = lane >> 2;
                int col0 = wc * 32 + (lane & 3) * 2;
#pragma unroll
                for (int mt = 0; mt < 2; mt++) {
                    int ja = wr * 32 + mt * 16 + row_lo;
                    int jb = ja + 8;
                    bool oka = ja < cnt, okb = jb < cnt;
                    float ga = sh_g[ja], gb = sh_g[jb];
                    float* da = g_yscat + (size_t)sh_f[ja] * D + col0;
                    float* db = g_yscat + (size_t)sh_f[jb] * D + col0;
#pragma unroll
                    for (int nt = 0; nt < 4; nt++) {
                        if (oka) {
                            float2 v = make_float2(acc[mt][nt][0] * ga, acc[mt][nt][1] * ga);
                            *(float2*)(da + nt * 8) = v;
                        }
                        if (okb) {
                            float2 v = make_float2(acc[mt][nt][2] * gb, acc[mt][nt][3] * gb);
                            *(float2*)(db + nt * 8) = v;
                        }
                    }
                }
            }

            e = en; s0 = s0n; cnt = cntn; fcur = fnxt; gcur = gnxt;
        }
    }

    // ---- grid barrier ----
    __threadfence();
    __syncthreads();
    if (tid == 0) {
        atomicAdd(&g_bar, 1u);
        unsigned v;
        do {
            asm volatile("ld.global.acquire.gpu.u32 %0, [%1];" : "=r"(v) : "l"(&g_bar));
            if (v >= (unsigned)gridDim.x) break;
            __nanosleep(128);
        } while (true);
    }
    __syncthreads();

    // ---- fused combine: out[n] = y[2n] + y[2n+1] ----
    {
        const float4* y4 = (const float4*)g_yscat;
        size_t total = (size_t)N_TOK * D / 4;
        size_t stride = (size_t)gridDim.x * NTHREADS;
        for (size_t idx = (size_t)blockIdx.x * NTHREADS + tid; idx < total; idx += stride) {
            size_t n = idx >> 5;
            int d4 = (int)(idx & 31);
            float4 a = y4[n * 64 + d4];
            float4 b = y4[n * 64 + 32 + d4];
            ((float4*)out)[idx] = make_float4(a.x + b.x, a.y + b.y, a.z + b.z, a.w + b.w);
        }
    }
}

// -------------------------------------------------------------------
extern "C" void kernel_launch(void* const* d_in, const int* in_sizes, int n_in,
                              void* d_out, int out_size) {
    const float* inputs = (const float*)d_in[0];
    const float* weight = (const float*)d_in[1];
    const float* gates  = (const float*)d_in[2];
    const int*   sei    = (const int*)d_in[4];
    const int*   ssi    = (const int*)d_in[5];
    float* out = (float*)d_out;

    int nsm = 148;
    cudaDeviceGetAttribute(&nsm, cudaDevAttrMultiProcessorCount, 0);

    cudaFuncSetAttribute(moe_fused_kernel,
                         cudaFuncAttributeMaxDynamicSharedMemorySize, SMEM_TOTAL);

    wconv_kernel<<<NEXP, 256>>>(weight);
    seg_kernel<<<1, 32>>>(sei);

    moe_fused_kernel<<<nsm, NTHREADS, SMEM_TOTAL>>>(inputs, gates, ssi, out);
}

// round 6
// speedup vs baseline: 1.2347x; 1.2347x over previous
#include <cuda_runtime.h>
#include <cuda_fp16.h>
#include <cstdint>

// ---------------- problem constants ----------------
#define N_TOK   262144
#define TOPK    2
#define NSLOTS  (N_TOK * TOPK)     // 524288
#define D       128
#define NEXP    8
#define TS      128                // slots per tile
#define MAXTILES (NSLOTS / TS + NEXP)   // 4104

// ---------------- device scratch ----------------
__device__ float g_yscat[(size_t)NSLOTS * D];    // gated per-slot outputs (256 MiB)
__device__ uint4 g_whp[NEXP * 2048];             // W hi fp16, packed [e][out][k] (32KB/expert)
__device__ uint4 g_wlp[NEXP * 2048];             // W lo fp16 (residual), packed
__device__ int   g_seg[NEXP + 1];
__device__ int   g_tile_e[MAXTILES];
__device__ int   g_tile_s[MAXTILES];
__device__ int   g_ntiles;

// ---------------- helpers ----------------
__device__ __forceinline__ uint32_t smem_u32(const void* p) {
    uint32_t a;
    asm("{ .reg .u64 t; cvta.to.shared.u64 t, %1; cvt.u32.u64 %0, t; }" : "=r"(a) : "l"(p));
    return a;
}
__device__ __forceinline__ void ldsm_x4(uint32_t* r, uint32_t addr) {
    asm volatile("ldmatrix.sync.aligned.m8n8.x4.shared.b16 {%0,%1,%2,%3}, [%4];"
        : "=r"(r[0]), "=r"(r[1]), "=r"(r[2]), "=r"(r[3]) : "r"(addr));
}
__device__ __forceinline__ void mma_fp16(float* c, const uint32_t* a, uint32_t b0, uint32_t b1) {
    asm volatile("mma.sync.aligned.m16n8k16.row.col.f32.f16.f16.f32 "
        "{%0,%1,%2,%3}, {%4,%5,%6,%7}, {%8,%9}, {%0,%1,%2,%3};"
        : "+f"(c[0]), "+f"(c[1]), "+f"(c[2]), "+f"(c[3])
        : "r"(a[0]), "r"(a[1]), "r"(a[2]), "r"(a[3]), "r"(b0), "r"(b1));
}
#define CP_ASYNC16(dst, src) \
    asm volatile("cp.async.cg.shared.global [%0], [%1], 16;" :: "r"(dst), "l"(src))
#define CP_COMMIT()  asm volatile("cp.async.commit_group;" ::: "memory")
#define CP_WAIT0()   asm volatile("cp.async.wait_group 0;" ::: "memory")

// convert 8 fp32 -> fp16 hi + fp16 residual (16 B each)
__device__ __forceinline__ void cvt8hl(const float* v, uint4& hv, uint4& lv) {
    __half h[8]; float l[8];
#pragma unroll
    for (int i = 0; i < 8; i++) {
        h[i] = __float2half_rn(v[i]);
        l[i] = v[i] - __half2float(h[i]);
    }
    uint32_t hu[4], lu[4];
#pragma unroll
    for (int i = 0; i < 4; i++) {
        __half2 hp = __halves2half2(h[2 * i], h[2 * i + 1]);
        hu[i] = *reinterpret_cast<uint32_t*>(&hp);
        __half2 lp = __floats2half2_rn(l[2 * i], l[2 * i + 1]);
        lu[i] = *reinterpret_cast<uint32_t*>(&lp);
    }
    hv = make_uint4(hu[0], hu[1], hu[2], hu[3]);
    lv = make_uint4(lu[0], lu[1], lu[2], lu[3]);
}

// convert 8 fp32 -> fp16 hi only
__device__ __forceinline__ uint4 cvt8h(const float* v) {
    uint32_t hu[4];
#pragma unroll
    for (int i = 0; i < 4; i++) {
        __half2 hp = __floats2half2_rn(v[2 * i], v[2 * i + 1]);
        hu[i] = *reinterpret_cast<uint32_t*>(&hp);
    }
    return make_uint4(hu[0], hu[1], hu[2], hu[3]);
}

// -------------------------------------------------------------------
// Prologue 1: weight fp32 [E, d_out, d_in] -> packed fp16 hi/lo
// -------------------------------------------------------------------
__global__ void wconv_kernel(const float* __restrict__ w) {
    int e = blockIdx.x;
    int tid = threadIdx.x;
    int row = tid >> 1;
    int half = tid & 1;
    const float* wr = w + ((size_t)e * D + row) * D;
    uint4* whe = g_whp + e * 2048;
    uint4* wle = g_wlp + e * 2048;
#pragma unroll
    for (int g = 0; g < 8; g++) {
        int col0 = half * 64 + g * 8;
        float v[8];
#pragma unroll
        for (int i = 0; i < 8; i++) v[i] = wr[col0 + i];
        uint4 hv, lv;
        cvt8hl(v, hv, lv);
        int idx = row * 16 + half * 8 + g;
        whe[idx] = hv;
        wle[idx] = lv;
    }
}

// -------------------------------------------------------------------
// Prologue 2: expert segments + dense tile map
// -------------------------------------------------------------------
__global__ void seg_kernel(const int* __restrict__ sei) {
    __shared__ int seg[NEXP + 1];
    __shared__ int cnts[NEXP];
    int t = threadIdx.x;
    if (t <= NEXP) {
        int lo = 0, hi = NSLOTS;
        while (lo < hi) {
            int mid = (lo + hi) >> 1;
            if (sei[mid] < t) lo = mid + 1; else hi = mid;
        }
        seg[t] = lo;
        g_seg[t] = lo;
    }
    __syncthreads();
    if (t < NEXP) cnts[t] = (seg[t + 1] - seg[t] + TS - 1) / TS;
    __syncthreads();
    if (t < NEXP) {
        int off = 0;
        for (int i = 0; i < t; i++) off += cnts[i];
        int s = seg[t];
        for (int i = 0; i < cnts[t]; i++) {
            g_tile_e[off + i] = t;
            g_tile_s[off + i] = s + i * TS;
        }
    }
    if (t == 0) {
        int tot = 0;
        for (int i = 0; i < NEXP; i++) tot += cnts[i];
        g_ntiles = tot;
    }
}

// -------------------------------------------------------------------
// SMEM layout
// -------------------------------------------------------------------
#define XROWB 272
#define IMGB  (128 * XROWB)          // 34816
#define RAWS  528                    // raw fp32 row stride (bytes)
#define RAWB  (128 * RAWS)           // 67584
#define OFF_SHF 0
#define OFF_SHG 512
#define OFF_RAW 1024
#define OFF_XH  (OFF_RAW + RAWB)     // 68608
#define OFF_WH  (OFF_XH + IMGB)      // 103424
#define OFF_WL  (OFF_WH + IMGB)      // 138240
#define SMEM_TOTAL (OFF_WL + IMGB)   // 173056

// issue cp.async gather of one X row-half per thread (16 x 16B)
__device__ __forceinline__ void issue_x(const float* __restrict__ x, int tok,
                                        int tid, uint32_t sb) {
    uint32_t dst = sb + OFF_RAW + (uint32_t)(tid >> 1) * RAWS + (tid & 1) * 256;
    const char* src = (const char*)(x + (size_t)tok * D) + (tid & 1) * 256;
#pragma unroll
    for (int c = 0; c < 16; c++)
        CP_ASYNC16(dst + c * 16, src + c * 16);
}

// -------------------------------------------------------------------
// Main: persistent fp16 2-term HMMA GEMM, W reuse + cp.async X pipeline
// -------------------------------------------------------------------
extern "C" __global__ void __launch_bounds__(256, 1)
moe_mma_kernel(const float* __restrict__ x,
               const float* __restrict__ gates,
               const int*   __restrict__ ssi) {
    int ntiles = g_ntiles;
    int nc = gridDim.x;
    int per = ntiles / nc, rem = ntiles % nc;
    int t0 = blockIdx.x * per + min((int)blockIdx.x, rem);
    int t1 = t0 + per + (blockIdx.x < rem ? 1 : 0);
    if (t0 >= t1) return;

    extern __shared__ char smem[];
    uint32_t sb = smem_u32(smem);
    int*   sh_f = (int*)(smem + OFF_SHF);
    float* sh_g = (float*)(smem + OFF_SHG);

    int tid = threadIdx.x;
    int wid = tid >> 5;
    int lane = tid & 31;
    int r = tid >> 1;                 // staging row

    // warp tiles: wr 0..3 (32 slots), wc 0..1 (64 outs)
    int wr = wid & 3;
    int wc = wid >> 2;
    int lrow = (lane & 7) | (lane & 8);
    int kby  = (lane >> 4) * 16;
    uint32_t aA = sb + OFF_XH + (uint32_t)(wr * 32 + lrow) * XROWB + kby;
    uint32_t aB = sb + OFF_WH + (uint32_t)(wc * 64 + lrow) * XROWB + kby;
    const uint32_t DLW = IMGB;        // WH -> WL image delta

    // ---- prime tile t0 ----
    int e  = g_tile_e[t0];
    int s0 = g_tile_s[t0];
    int cnt = min(TS, g_seg[e + 1] - s0);
    int   fcur = (r < cnt) ? ssi[s0 + r] : 0;
    float gcur = (r < cnt) ? gates[fcur] : 0.f;
    issue_x(x, fcur >> 1, tid, sb);   // TOPK == 2
    CP_COMMIT();

    int staged_e = -1;

    for (int t = t0; t < t1; t++) {
        // ---- prefetch metadata for t+1 ----
        bool havenext = (t + 1 < t1);
        int en = e, s0n = s0, cntn = cnt, fnxt = 0; float gnxt = 0.f;
        if (havenext) {
            en  = g_tile_e[t + 1];
            s0n = g_tile_s[t + 1];
            cntn = min(TS, g_seg[en + 1] - s0n);
            fnxt = (r < cntn) ? ssi[s0n + r] : 0;
            gnxt = (r < cntn) ? gates[fnxt] : 0.f;
        }

        CP_WAIT0();            // raw(t) resident
        __syncthreads();       // publish raw; prior tile fully consumed

        // ---- stage W on expert change (rare) ----
        if (e != staged_e) {
            const uint4* whe = g_whp + e * 2048;
            const uint4* wle = g_wlp + e * 2048;
#pragma unroll
            for (int i = 0; i < 8; i++) {
                int cid = tid + 256 * i;
                int row = cid >> 4;
                int w16 = cid & 15;
                uint32_t doff = row * XROWB + w16 * 16;
                *(uint4*)(smem + OFF_WH + doff) = whe[cid];
                *(uint4*)(smem + OFF_WL + doff) = wle[cid];
            }
            staged_e = e;
        }

        // ---- metadata to smem ----
        if (!(tid & 1)) {
            sh_f[r] = fcur;
            sh_g[r] = gcur;
        }

        // ---- convert raw fp32 -> fp16 image (hi only) ----
        {
            int half = tid & 1;
            const char* rp = smem + OFF_RAW + (uint32_t)r * RAWS + half * 256;
            char* xh = smem + OFF_XH;
#pragma unroll
            for (int g = 0; g < 8; g++) {
                float4 a = *(const float4*)(rp + g * 32);
                float4 b = *(const float4*)(rp + g * 32 + 16);
                float v[8] = {a.x, a.y, a.z, a.w, b.x, b.y, b.z, b.w};
                uint4 hv = cvt8h(v);
                uint32_t off = (uint32_t)r * XROWB + (half * 64 + g * 8) * 2;
                *(uint4*)(xh + off) = hv;
            }
        }
        __syncthreads();       // image + meta ready; raw drained

        // ---- kick gather for t+1 (overlaps with MMA) ----
        if (havenext) {
            issue_x(x, fnxt >> 1, tid, sb);
            CP_COMMIT();
        }

        // ---- MMA: fp16 2-term (xh*wh + xh*wl) ----
        float acc[2][8][4];
#pragma unroll
        for (int mt = 0; mt < 2; mt++)
#pragma unroll
            for (int nt = 0; nt < 8; nt++)
#pragma unroll
                for (int i = 0; i < 4; i++) acc[mt][nt][i] = 0.f;

#pragma unroll
        for (int kk = 0; kk < 8; kk++) {
            uint32_t kb = kk * 32;
            uint32_t ah[2][4];
            ldsm_x4(ah[0], aA + kb);
            ldsm_x4(ah[1], aA + 16 * XROWB + kb);
#pragma unroll
            for (int ng = 0; ng < 4; ng++) {
                uint32_t bh[4], bl[4];
                ldsm_x4(bh, aB + ng * 16 * XROWB + kb);
                ldsm_x4(bl, aB + DLW + ng * 16 * XROWB + kb);
#pragma unroll
                for (int mt = 0; mt < 2; mt++) {
                    mma_fp16(acc[mt][2 * ng],     ah[mt], bh[0], bh[2]);
                    mma_fp16(acc[mt][2 * ng + 1], ah[mt], bh[1], bh[3]);
                    mma_fp16(acc[mt][2 * ng],     ah[mt], bl[0], bl[2]);
                    mma_fp16(acc[mt][2 * ng + 1], ah[mt], bl[1], bl[3]);
                }
            }
        }

        // ---- epilogue: gate + scatter ----
        {
            int row_lo = lane >> 2;
            int col0 = wc * 64 + (lane & 3) * 2;
#pragma unroll
            for (int mt = 0; mt < 2; mt++) {
                int ja = wr * 32 + mt * 16 + row_lo;
                int jb = ja + 8;
                bool oka = ja < cnt, okb = jb < cnt;
                float ga = sh_g[ja], gb = sh_g[jb];
                float* da = g_yscat + (size_t)sh_f[ja] * D + col0;
                float* db = g_yscat + (size_t)sh_f[jb] * D + col0;
#pragma unroll
                for (int nt = 0; nt < 8; nt++) {
                    if (oka) {
                        float2 v = make_float2(acc[mt][nt][0] * ga, acc[mt][nt][1] * ga);
                        *(float2*)(da + nt * 8) = v;
                    }
                    if (okb) {
                        float2 v = make_float2(acc[mt][nt][2] * gb, acc[mt][nt][3] * gb);
                        *(float2*)(db + nt * 8) = v;
                    }
                }
            }
        }

        // rotate tile state
        e = en; s0 = s0n; cnt = cntn; fcur = fnxt; gcur = gnxt;
    }
}

// -------------------------------------------------------------------
// combine: out[n] = y[2n] + y[2n+1]  (at DRAM roofline)
// -------------------------------------------------------------------
__global__ void combine_kernel(float* __restrict__ out) {
    size_t idx = (size_t)blockIdx.x * blockDim.x + threadIdx.x;
    const float4* y4 = (const float4*)g_yscat;
    size_t n = idx >> 5;
    int d4 = (int)(idx & 31);
    float4 a = y4[n * 64 + d4];
    float4 b = y4[n * 64 + 32 + d4];
    ((float4*)out)[idx] = make_float4(a.x + b.x, a.y + b.y, a.z + b.z, a.w + b.w);
}

// -------------------------------------------------------------------
extern "C" void kernel_launch(void* const* d_in, const int* in_sizes, int n_in,
                              void* d_out, int out_size) {
    const float* inputs = (const float*)d_in[0];
    const float* weight = (const float*)d_in[1];
    const float* gates  = (const float*)d_in[2];
    const int*   sei    = (const int*)d_in[4];
    const int*   ssi    = (const int*)d_in[5];
    float* out = (float*)d_out;

    int nsm = 148;
    cudaDeviceGetAttribute(&nsm, cudaDevAttrMultiProcessorCount, 0);

    cudaFuncSetAttribute(moe_mma_kernel,
                         cudaFuncAttributeMaxDynamicSharedMemorySize, SMEM_TOTAL);

    wconv_kernel<<<NEXP, 256>>>(weight);
    seg_kernel<<<1, 32>>>(sei);

    moe_mma_kernel<<<nsm, 256, SMEM_TOTAL>>>(inputs, gates, ssi);

    combine_kernel<<<(N_TOK * D / 4) / 256, 256>>>(out);
}

// round 7
// speedup vs baseline: 1.4954x; 1.2111x over previous
#include <cuda_runtime.h>
#include <cuda_fp16.h>
#include <cstdint>

// ---------------- problem constants ----------------
#define N_TOK   262144
#define TOPK    2
#define NSLOTS  (N_TOK * TOPK)     // 524288
#define D       128
#define NEXP    8
#define TS      128                // slots per tile
#define MAXTILES (NSLOTS / TS + NEXP)   // 4104

// ---------------- device scratch ----------------
__device__ uint4 g_whp[NEXP * 2048];             // W fp16, packed [e][out][k] (32KB/expert)
__device__ int   g_seg[NEXP + 1];
__device__ int   g_tile_e[MAXTILES];
__device__ int   g_tile_s[MAXTILES];
__device__ int   g_ntiles;

// ---------------- helpers ----------------
__device__ __forceinline__ uint32_t smem_u32(const void* p) {
    uint32_t a;
    asm("{ .reg .u64 t; cvta.to.shared.u64 t, %1; cvt.u32.u64 %0, t; }" : "=r"(a) : "l"(p));
    return a;
}
__device__ __forceinline__ void ldsm_x4(uint32_t* r, uint32_t addr) {
    asm volatile("ldmatrix.sync.aligned.m8n8.x4.shared.b16 {%0,%1,%2,%3}, [%4];"
        : "=r"(r[0]), "=r"(r[1]), "=r"(r[2]), "=r"(r[3]) : "r"(addr));
}
__device__ __forceinline__ void mma_fp16(float* c, const uint32_t* a, uint32_t b0, uint32_t b1) {
    asm volatile("mma.sync.aligned.m16n8k16.row.col.f32.f16.f16.f32 "
        "{%0,%1,%2,%3}, {%4,%5,%6,%7}, {%8,%9}, {%0,%1,%2,%3};"
        : "+f"(c[0]), "+f"(c[1]), "+f"(c[2]), "+f"(c[3])
        : "r"(a[0]), "r"(a[1]), "r"(a[2]), "r"(a[3]), "r"(b0), "r"(b1));
}
#define CP_ASYNC16(dst, src) \
    asm volatile("cp.async.cg.shared.global [%0], [%1], 16;" :: "r"(dst), "l"(src))
#define CP_COMMIT()  asm volatile("cp.async.commit_group;" ::: "memory")
#define CP_WAIT0()   asm volatile("cp.async.wait_group 0;" ::: "memory")
#define RED_ADD_V2(ptr, a, b) \
    asm volatile("red.global.add.v2.f32 [%0], {%1, %2};" :: "l"(ptr), "f"(a), "f"(b) : "memory")

// convert 8 fp32 -> fp16 (16 B)
__device__ __forceinline__ uint4 cvt8h(const float* v) {
    uint32_t hu[4];
#pragma unroll
    for (int i = 0; i < 4; i++) {
        __half2 hp = __floats2half2_rn(v[2 * i], v[2 * i + 1]);
        hu[i] = *reinterpret_cast<uint32_t*>(&hp);
    }
    return make_uint4(hu[0], hu[1], hu[2], hu[3]);
}

// -------------------------------------------------------------------
// Prologue 1: weight fp32 [E, d_out, d_in] -> packed fp16
// -------------------------------------------------------------------
__global__ void wconv_kernel(const float* __restrict__ w) {
    int e = blockIdx.x;
    int tid = threadIdx.x;
    int row = tid >> 1;
    int half = tid & 1;
    const float* wr = w + ((size_t)e * D + row) * D;
    uint4* whe = g_whp + e * 2048;
#pragma unroll
    for (int g = 0; g < 8; g++) {
        int col0 = half * 64 + g * 8;
        float v[8];
#pragma unroll
        for (int i = 0; i < 8; i++) v[i] = wr[col0 + i];
        whe[row * 16 + half * 8 + g] = cvt8h(v);
    }
}

// -------------------------------------------------------------------
// Prologue 2: expert segments + dense tile map
// -------------------------------------------------------------------
__global__ void seg_kernel(const int* __restrict__ sei) {
    __shared__ int seg[NEXP + 1];
    __shared__ int cnts[NEXP];
    int t = threadIdx.x;
    if (t <= NEXP) {
        int lo = 0, hi = NSLOTS;
        while (lo < hi) {
            int mid = (lo + hi) >> 1;
            if (sei[mid] < t) lo = mid + 1; else hi = mid;
        }
        seg[t] = lo;
        g_seg[t] = lo;
    }
    __syncthreads();
    if (t < NEXP) cnts[t] = (seg[t + 1] - seg[t] + TS - 1) / TS;
    __syncthreads();
    if (t < NEXP) {
        int off = 0;
        for (int i = 0; i < t; i++) off += cnts[i];
        int s = seg[t];
        for (int i = 0; i < cnts[t]; i++) {
            g_tile_e[off + i] = t;
            g_tile_s[off + i] = s + i * TS;
        }
    }
    if (t == 0) {
        int tot = 0;
        for (int i = 0; i < NEXP; i++) tot += cnts[i];
        g_ntiles = tot;
    }
}

// -------------------------------------------------------------------
// Prologue 3: zero-init out (atomic accumulation target)
// -------------------------------------------------------------------
__global__ void zero_kernel(float4* __restrict__ out) {
    size_t idx = (size_t)blockIdx.x * blockDim.x + threadIdx.x;
    out[idx] = make_float4(0.f, 0.f, 0.f, 0.f);
}

// -------------------------------------------------------------------
// SMEM layout
// -------------------------------------------------------------------
#define XROWB 272
#define IMGB  (128 * XROWB)          // 34816
#define RAWS  528                    // raw fp32 row stride (bytes)
#define RAWB  (128 * RAWS)           // 67584
#define OFF_SHF 0
#define OFF_SHG 512
#define OFF_RAW 1024
#define OFF_XH  (OFF_RAW + RAWB)     // 68608
#define OFF_WH  (OFF_XH + IMGB)      // 103424
#define SMEM_TOTAL (OFF_WH + IMGB)   // 138240

// issue cp.async gather of one X row-half per thread (16 x 16B)
__device__ __forceinline__ void issue_x(const float* __restrict__ x, int tok,
                                        int tid, uint32_t sb) {
    uint32_t dst = sb + OFF_RAW + (uint32_t)(tid >> 1) * RAWS + (tid & 1) * 256;
    const char* src = (const char*)(x + (size_t)tok * D) + (tid & 1) * 256;
#pragma unroll
    for (int c = 0; c < 16; c++)
        CP_ASYNC16(dst + c * 16, src + c * 16);
}

// -------------------------------------------------------------------
// Main: persistent fp16 single-term HMMA GEMM + fused atomic epilogue
// -------------------------------------------------------------------
extern "C" __global__ void __launch_bounds__(256, 1)
moe_mma_kernel(const float* __restrict__ x,
               const float* __restrict__ gates,
               const int*   __restrict__ ssi,
               float* __restrict__ out) {
    int ntiles = g_ntiles;
    int nc = gridDim.x;
    int per = ntiles / nc, rem = ntiles % nc;
    int t0 = blockIdx.x * per + min((int)blockIdx.x, rem);
    int t1 = t0 + per + (blockIdx.x < rem ? 1 : 0);
    if (t0 >= t1) return;

    extern __shared__ char smem[];
    uint32_t sb = smem_u32(smem);
    int*   sh_f = (int*)(smem + OFF_SHF);
    float* sh_g = (float*)(smem + OFF_SHG);

    int tid = threadIdx.x;
    int wid = tid >> 5;
    int lane = tid & 31;
    int r = tid >> 1;                 // staging row

    // warp tiles: wr 0..3 (32 slots), wc 0..1 (64 outs)
    int wr = wid & 3;
    int wc = wid >> 2;
    int lrow = (lane & 7) | (lane & 8);
    int kby  = (lane >> 4) * 16;
    uint32_t aA = sb + OFF_XH + (uint32_t)(wr * 32 + lrow) * XROWB + kby;
    uint32_t aB = sb + OFF_WH + (uint32_t)(wc * 64 + lrow) * XROWB + kby;

    // ---- prime tile t0 ----
    int e  = g_tile_e[t0];
    int s0 = g_tile_s[t0];
    int cnt = min(TS, g_seg[e + 1] - s0);
    int   fcur = (r < cnt) ? ssi[s0 + r] : 0;
    float gcur = (r < cnt) ? gates[fcur] : 0.f;
    issue_x(x, fcur >> 1, tid, sb);   // TOPK == 2
    CP_COMMIT();

    int staged_e = -1;

    for (int t = t0; t < t1; t++) {
        // ---- prefetch metadata for t+1 ----
        bool havenext = (t + 1 < t1);
        int en = e, s0n = s0, cntn = cnt, fnxt = 0; float gnxt = 0.f;
        if (havenext) {
            en  = g_tile_e[t + 1];
            s0n = g_tile_s[t + 1];
            cntn = min(TS, g_seg[en + 1] - s0n);
            fnxt = (r < cntn) ? ssi[s0n + r] : 0;
            gnxt = (r < cntn) ? gates[fnxt] : 0.f;
        }

        CP_WAIT0();            // raw(t) resident
        __syncthreads();       // publish raw; prior tile fully consumed

        // ---- stage W on expert change (rare) ----
        if (e != staged_e) {
            const uint4* whe = g_whp + e * 2048;
#pragma unroll
            for (int i = 0; i < 8; i++) {
                int cid = tid + 256 * i;
                int row = cid >> 4;
                int w16 = cid & 15;
                *(uint4*)(smem + OFF_WH + row * XROWB + w16 * 16) = whe[cid];
            }
            staged_e = e;
        }

        // ---- metadata to smem ----
        if (!(tid & 1)) {
            sh_f[r] = fcur;
            sh_g[r] = gcur;
        }

        // ---- convert raw fp32 -> fp16 image ----
        {
            int half = tid & 1;
            const char* rp = smem + OFF_RAW + (uint32_t)r * RAWS + half * 256;
            char* xh = smem + OFF_XH;
#pragma unroll
            for (int g = 0; g < 8; g++) {
                float4 a = *(const float4*)(rp + g * 32);
                float4 b = *(const float4*)(rp + g * 32 + 16);
                float v[8] = {a.x, a.y, a.z, a.w, b.x, b.y, b.z, b.w};
                uint4 hv = cvt8h(v);
                *(uint4*)(xh + (uint32_t)r * XROWB + (half * 64 + g * 8) * 2) = hv;
            }
        }
        __syncthreads();       // image + meta ready; raw drained

        // ---- kick gather for t+1 (overlaps with MMA) ----
        if (havenext) {
            issue_x(x, fnxt >> 1, tid, sb);
            CP_COMMIT();
        }

        // ---- MMA: single fp16 pass ----
        float acc[2][8][4];
#pragma unroll
        for (int mt = 0; mt < 2; mt++)
#pragma unroll
            for (int nt = 0; nt < 8; nt++)
#pragma unroll
                for (int i = 0; i < 4; i++) acc[mt][nt][i] = 0.f;

#pragma unroll
        for (int kk = 0; kk < 8; kk++) {
            uint32_t kb = kk * 32;
            uint32_t ah[2][4];
            ldsm_x4(ah[0], aA + kb);
            ldsm_x4(ah[1], aA + 16 * XROWB + kb);
#pragma unroll
            for (int ng = 0; ng < 4; ng++) {
                uint32_t bh[4];
                ldsm_x4(bh, aB + ng * 16 * XROWB + kb);
#pragma unroll
                for (int mt = 0; mt < 2; mt++) {
                    mma_fp16(acc[mt][2 * ng],     ah[mt], bh[0], bh[2]);
                    mma_fp16(acc[mt][2 * ng + 1], ah[mt], bh[1], bh[3]);
                }
            }
        }

        // ---- fused epilogue: gate + atomic-add into out ----
        // each out element receives exactly TOPK=2 adds -> order-independent
        {
            int row_lo = lane >> 2;
            int col0 = wc * 64 + (lane & 3) * 2;
#pragma unroll
            for (int mt = 0; mt < 2; mt++) {
                int ja = wr * 32 + mt * 16 + row_lo;
                int jb = ja + 8;
                bool oka = ja < cnt, okb = jb < cnt;
                float ga = sh_g[ja], gb = sh_g[jb];
                float* da = out + (size_t)(sh_f[ja] >> 1) * D + col0;
                float* db = out + (size_t)(sh_f[jb] >> 1) * D + col0;
#pragma unroll
                for (int nt = 0; nt < 8; nt++) {
                    if (oka)
                        RED_ADD_V2(da + nt * 8, acc[mt][nt][0] * ga, acc[mt][nt][1] * ga);
                    if (okb)
                        RED_ADD_V2(db + nt * 8, acc[mt][nt][2] * gb, acc[mt][nt][3] * gb);
                }
            }
        }

        // rotate tile state
        e = en; s0 = s0n; cnt = cntn; fcur = fnxt; gcur = gnxt;
    }
}

// -------------------------------------------------------------------
extern "C" void kernel_launch(void* const* d_in, const int* in_sizes, int n_in,
                              void* d_out, int out_size) {
    const float* inputs = (const float*)d_in[0];
    const float* weight = (const float*)d_in[1];
    const float* gates  = (const float*)d_in[2];
    const int*   sei    = (const int*)d_in[4];
    const int*   ssi    = (const int*)d_in[5];
    float* out = (float*)d_out;

    int nsm = 148;
    cudaDeviceGetAttribute(&nsm, cudaDevAttrMultiProcessorCount, 0);

    cudaFuncSetAttribute(moe_mma_kernel,
                         cudaFuncAttributeMaxDynamicSharedMemorySize, SMEM_TOTAL);

    wconv_kernel<<<NEXP, 256>>>(weight);
    seg_kernel<<<1, 32>>>(sei);
    zero_kernel<<<(N_TOK * D / 4) / 256, 256>>>((float4*)out);

    moe_mma_kernel<<<nsm, 256, SMEM_TOTAL>>>(inputs, gates, ssi, out);
}

// round 8
// speedup vs baseline: 1.8059x; 1.2077x over previous
#include <cuda_runtime.h>
#include <cuda_fp16.h>
#include <cstdint>

// ---------------- problem constants ----------------
#define N_TOK   262144
#define TOPK    2
#define NSLOTS  (N_TOK * TOPK)     // 524288
#define D       128
#define NEXP    8
#define TS      128                // slots per tile
#define MAXTILES (NSLOTS / TS + NEXP)   // 4104

// ---------------- device scratch ----------------
__device__ uint4 g_whp[NEXP * 2048];             // W fp16, packed [e][out][k] (32KB/expert)
__device__ int   g_seg[NEXP + 1];
__device__ int   g_tile_e[MAXTILES];
__device__ int   g_tile_s[MAXTILES];
__device__ int   g_ntiles;

// ---------------- helpers ----------------
__device__ __forceinline__ uint32_t smem_u32(const void* p) {
    uint32_t a;
    asm("{ .reg .u64 t; cvta.to.shared.u64 t, %1; cvt.u32.u64 %0, t; }" : "=r"(a) : "l"(p));
    return a;
}
__device__ __forceinline__ void ldsm_x4(uint32_t* r, uint32_t addr) {
    asm volatile("ldmatrix.sync.aligned.m8n8.x4.shared.b16 {%0,%1,%2,%3}, [%4];"
        : "=r"(r[0]), "=r"(r[1]), "=r"(r[2]), "=r"(r[3]) : "r"(addr));
}
__device__ __forceinline__ void mma_fp16(float* c, const uint32_t* a, uint32_t b0, uint32_t b1) {
    asm volatile("mma.sync.aligned.m16n8k16.row.col.f32.f16.f16.f32 "
        "{%0,%1,%2,%3}, {%4,%5,%6,%7}, {%8,%9}, {%0,%1,%2,%3};"
        : "+f"(c[0]), "+f"(c[1]), "+f"(c[2]), "+f"(c[3])
        : "r"(a[0]), "r"(a[1]), "r"(a[2]), "r"(a[3]), "r"(b0), "r"(b1));
}
#define RED_ADD_V2(ptr, a, b) \
    asm volatile("red.global.add.v2.f32 [%0], {%1, %2};" :: "l"(ptr), "f"(a), "f"(b) : "memory")

// convert 8 fp32 -> fp16 (16 B)
__device__ __forceinline__ uint4 cvt8h(const float* v) {
    uint32_t hu[4];
#pragma unroll
    for (int i = 0; i < 4; i++) {
        __half2 hp = __floats2half2_rn(v[2 * i], v[2 * i + 1]);
        hu[i] = *reinterpret_cast<uint32_t*>(&hp);
    }
    return make_uint4(hu[0], hu[1], hu[2], hu[3]);
}

// -------------------------------------------------------------------
// Prologue 1: weight fp32 [E, d_out, d_in] -> packed fp16
// -------------------------------------------------------------------
__global__ void wconv_kernel(const float* __restrict__ w) {
    int e = blockIdx.x;
    int tid = threadIdx.x;
    int row = tid >> 1;
    int half = tid & 1;
    const float* wr = w + ((size_t)e * D + row) * D;
    uint4* whe = g_whp + e * 2048;
#pragma unroll
    for (int g = 0; g < 8; g++) {
        int col0 = half * 64 + g * 8;
        float v[8];
#pragma unroll
        for (int i = 0; i < 8; i++) v[i] = wr[col0 + i];
        whe[row * 16 + half * 8 + g] = cvt8h(v);
    }
}

// -------------------------------------------------------------------
// Prologue 2: expert segments + dense tile map
// -------------------------------------------------------------------
__global__ void seg_kernel(const int* __restrict__ sei) {
    __shared__ int seg[NEXP + 1];
    __shared__ int cnts[NEXP];
    int t = threadIdx.x;
    if (t <= NEXP) {
        int lo = 0, hi = NSLOTS;
        while (lo < hi) {
            int mid = (lo + hi) >> 1;
            if (sei[mid] < t) lo = mid + 1; else hi = mid;
        }
        seg[t] = lo;
        g_seg[t] = lo;
    }
    __syncthreads();
    if (t < NEXP) cnts[t] = (seg[t + 1] - seg[t] + TS - 1) / TS;
    __syncthreads();
    if (t < NEXP) {
        int off = 0;
        for (int i = 0; i < t; i++) off += cnts[i];
        int s = seg[t];
        for (int i = 0; i < cnts[t]; i++) {
            g_tile_e[off + i] = t;
            g_tile_s[off + i] = s + i * TS;
        }
    }
    if (t == 0) {
        int tot = 0;
        for (int i = 0; i < NEXP; i++) tot += cnts[i];
        g_ntiles = tot;
    }
}

// -------------------------------------------------------------------
// Prologue 3: zero-init out (atomic accumulation target)
// -------------------------------------------------------------------
__global__ void zero_kernel(float4* __restrict__ out) {
    size_t idx = (size_t)blockIdx.x * blockDim.x + threadIdx.x;
    out[idx] = make_float4(0.f, 0.f, 0.f, 0.f);
}

// -------------------------------------------------------------------
// SMEM layout (69 KB -> 2 CTAs/SM)
// -------------------------------------------------------------------
#define XROWB 272
#define IMGB  (128 * XROWB)          // 34816
#define OFF_SHF 0
#define OFF_SHG 512
#define OFF_XH  1024
#define OFF_WH  (OFF_XH + IMGB)      // 35840
#define SMEM_TOTAL (OFF_WH + IMGB)   // 70656

// -------------------------------------------------------------------
// Main: persistent fp16 HMMA GEMM, 2 CTAs/SM, LDG gather + fused atomics
// -------------------------------------------------------------------
extern "C" __global__ void __launch_bounds__(256, 2)
moe_mma_kernel(const float* __restrict__ x,
               const float* __restrict__ gates,
               const int*   __restrict__ ssi,
               float* __restrict__ out) {
    int ntiles = g_ntiles;
    int nc = gridDim.x;
    int per = ntiles / nc, rem = ntiles % nc;
    int t0 = blockIdx.x * per + min((int)blockIdx.x, rem);
    int t1 = t0 + per + (blockIdx.x < rem ? 1 : 0);
    if (t0 >= t1) return;

    extern __shared__ char smem[];
    uint32_t sb = smem_u32(smem);
    int*   sh_f = (int*)(smem + OFF_SHF);
    float* sh_g = (float*)(smem + OFF_SHG);

    int tid = threadIdx.x;
    int wid = tid >> 5;
    int lane = tid & 31;
    int r = tid >> 1;                 // staging row (2 threads per row)
    int half = tid & 1;

    // warp tiles: wr 0..3 (32 slots), wc 0..1 (64 outs)
    int wr = wid & 3;
    int wc = wid >> 2;
    int lrow = (lane & 7) | (lane & 8);
    int kby  = (lane >> 4) * 16;
    uint32_t aA = sb + OFF_XH + (uint32_t)(wr * 32 + lrow) * XROWB + kby;
    uint32_t aB = sb + OFF_WH + (uint32_t)(wc * 64 + lrow) * XROWB + kby;

    // ---- prime tile t0 metadata ----
    int e  = g_tile_e[t0];
    int s0 = g_tile_s[t0];
    int cnt = min(TS, g_seg[e + 1] - s0);
    int   fcur = (r < cnt) ? ssi[s0 + r] : 0;
    float gcur = (r < cnt) ? gates[fcur] : 0.f;

    int staged_e = -1;

    for (int t = t0; t < t1; t++) {
        // ---- issue X gather for this tile (LDG latency overlaps prev tail+sync) ----
        float4 xr[8];
        {
            const float4* xp = (const float4*)x + (size_t)(fcur >> 1) * 32 + half * 16;
#pragma unroll
            for (int g = 0; g < 8; g++) xr[g] = xp[g * 2];      // 8 x 16B, covers half row
#pragma unroll
            for (int g = 0; g < 8; g++) {
                float4 b = xp[g * 2 + 1];
                // interleave: keep both float4s of each 32B chunk
                // (store b into xr upper half later via cvt below)
                // we convert pairwise below; stash b in registers:
                ((float4*)xr)[g] = xr[g];  // no-op to keep naming
                // store second half directly after first in cvt loop
                // handled below
                (void)b;
            }
        }
        // NOTE: simpler two-batch gather to limit live registers:
        // batch A = chunks 0..7 (first 16B of each 32B pair) done above;
        // we re-load batch B inside the convert loop (L1-hot, cheap).

        // ---- prefetch metadata for t+1 ----
        bool havenext = (t + 1 < t1);
        int en = e, s0n = s0, cntn = cnt, fnxt = 0; float gnxt = 0.f;
        if (havenext) {
            en  = g_tile_e[t + 1];
            s0n = g_tile_s[t + 1];
            cntn = min(TS, g_seg[en + 1] - s0n);
            fnxt = (r < cntn) ? ssi[s0n + r] : 0;
            gnxt = (r < cntn) ? gates[fnxt] : 0.f;
        }

        __syncthreads();       // prev tile MMA/epilogue done -> safe to overwrite images

        // ---- stage W on expert change (rare) ----
        if (e != staged_e) {
            const uint4* whe = g_whp + e * 2048;
#pragma unroll
            for (int i = 0; i < 8; i++) {
                int cid = tid + 256 * i;
                int row = cid >> 4;
                int w16 = cid & 15;
                *(uint4*)(smem + OFF_WH + row * XROWB + w16 * 16) = whe[cid];
            }
            staged_e = e;
        }

        // ---- metadata to smem ----
        if (!half) {
            sh_f[r] = fcur;
            sh_g[r] = gcur;
        }

        // ---- convert + STS fp16 image ----
        {
            const float4* xp = (const float4*)x + (size_t)(fcur >> 1) * 32 + half * 16;
            char* xh = smem + OFF_XH;
#pragma unroll
            for (int g = 0; g < 8; g++) {
                float4 a = xr[g];
                float4 b = xp[g * 2 + 1];      // L1-hot second half of chunk
                float v[8] = {a.x, a.y, a.z, a.w, b.x, b.y, b.z, b.w};
                uint4 hv = cvt8h(v);
                *(uint4*)(xh + (uint32_t)r * XROWB + (half * 64 + g * 8) * 2) = hv;
            }
        }
        __syncthreads();       // image + meta ready

        // ---- MMA: single fp16 pass ----
        float acc[2][8][4];
#pragma unroll
        for (int mt = 0; mt < 2; mt++)
#pragma unroll
            for (int nt = 0; nt < 8; nt++)
#pragma unroll
                for (int i = 0; i < 4; i++) acc[mt][nt][i] = 0.f;

#pragma unroll
        for (int kk = 0; kk < 8; kk++) {
            uint32_t kb = kk * 32;
            uint32_t ah[2][4];
            ldsm_x4(ah[0], aA + kb);
            ldsm_x4(ah[1], aA + 16 * XROWB + kb);
#pragma unroll
            for (int ng = 0; ng < 4; ng++) {
                uint32_t bh[4];
                ldsm_x4(bh, aB + ng * 16 * XROWB + kb);
#pragma unroll
                for (int mt = 0; mt < 2; mt++) {
                    mma_fp16(acc[mt][2 * ng],     ah[mt], bh[0], bh[2]);
                    mma_fp16(acc[mt][2 * ng + 1], ah[mt], bh[1], bh[3]);
                }
            }
        }

        // ---- fused epilogue: gate + atomic-add into out ----
        // each out element receives exactly TOPK=2 adds -> order-independent
        {
            int row_lo = lane >> 2;
            int col0 = wc * 64 + (lane & 3) * 2;
#pragma unroll
            for (int mt = 0; mt < 2; mt++) {
                int ja = wr * 32 + mt * 16 + row_lo;
                int jb = ja + 8;
                bool oka = ja < cnt, okb = jb < cnt;
                float ga = sh_g[ja], gb = sh_g[jb];
                float* da = out + (size_t)(sh_f[ja] >> 1) * D + col0;
                float* db = out + (size_t)(sh_f[jb] >> 1) * D + col0;
#pragma unroll
                for (int nt = 0; nt < 8; nt++) {
                    if (oka)
                        RED_ADD_V2(da + nt * 8, acc[mt][nt][0] * ga, acc[mt][nt][1] * ga);
                    if (okb)
                        RED_ADD_V2(db + nt * 8, acc[mt][nt][2] * gb, acc[mt][nt][3] * gb);
                }
            }
        }

        // rotate tile state
        e = en; s0 = s0n; cnt = cntn; fcur = fnxt; gcur = gnxt;
    }
}

// -------------------------------------------------------------------
extern "C" void kernel_launch(void* const* d_in, const int* in_sizes, int n_in,
                              void* d_out, int out_size) {
    const float* inputs = (const float*)d_in[0];
    const float* weight = (const float*)d_in[1];
    const float* gates  = (const float*)d_in[2];
    const int*   sei    = (const int*)d_in[4];
    const int*   ssi    = (const int*)d_in[5];
    float* out = (float*)d_out;

    int nsm = 148;
    cudaDeviceGetAttribute(&nsm, cudaDevAttrMultiProcessorCount, 0);

    cudaFuncSetAttribute(moe_mma_kernel,
                         cudaFuncAttributeMaxDynamicSharedMemorySize, SMEM_TOTAL);

    wconv_kernel<<<NEXP, 256>>>(weight);
    seg_kernel<<<1, 32>>>(sei);
    zero_kernel<<<(N_TOK * D / 4) / 256, 256>>>((float4*)out);

    moe_mma_kernel<<<2 * nsm, 256, SMEM_TOTAL>>>(inputs, gates, ssi, out);
}